// round 3
// baseline (speedup 1.0000x reference)
#include <cuda_runtime.h>
#include <cstdint>

// ---------------------------------------------------------------------------
// GAT hierarchical 2-layer, restructured (see R2 notes). This round: the
// attention kernel computes logits with NO shared-memory reads (register
// dot products fed by broadcast global loads), removing the 4-way LDS bank
// conflicts that made R2's attn kernel L1-bound.
// ---------------------------------------------------------------------------

// scratch layout (floats)
static constexpr size_t OFF_Y1 = 0;                        // [10240,512]
static constexpr size_t OFF_Y0 = OFF_Y1 + 10240ull * 512;  // [1024,512]
static constexpr size_t OFF_U  = OFF_Y0 + 1024ull * 512;   // [1024,2048]
static constexpr size_t OFF_V  = OFF_U  + 1024ull * 2048;  // [1024,2048]
static constexpr size_t OFF_H  = OFF_V  + 1024ull * 2048;  // [1024,512]
static constexpr size_t OFF_P0 = OFF_H  + 1024ull * 512;   // P0s[512],P0n[512]
static constexpr size_t OFF_P1 = OFF_P0 + 1024;            // P1s[2048],P1n[2048]
static constexpr size_t OFF_Q  = OFF_P1 + 4096;            // Qs[2048],Qn[2048]
static constexpr size_t SCRATCH_FLOATS = OFF_Q + 4096;

__device__ float g_scratch[SCRATCH_FLOATS];

// ---------------------------------------------------------------------------
__global__ void prep0_kernel(const float* __restrict__ W0,
                             const float* __restrict__ a0s,
                             const float* __restrict__ a0n,
                             float* __restrict__ P0)
{
    int t = blockIdx.x * blockDim.x + threadIdx.x;
    if (t >= 512) return;
    int h = t >> 7, f = t & 127;
    const float* wrow = W0 + (size_t)f * 512 + h * 128;
    const float* as = a0s + h * 128;
    const float* an = a0n + h * 128;
    float s = 0.f, n = 0.f;
    #pragma unroll 4
    for (int d = 0; d < 128; d++) {
        float wv = wrow[d];
        s = fmaf(wv, as[d], s);
        n = fmaf(wv, an[d], n);
    }
    P0[t] = s;
    P0[512 + t] = n;
}

__global__ void prep1_kernel(const float* __restrict__ W1,
                             const float* __restrict__ a1s,
                             const float* __restrict__ a1n,
                             float* __restrict__ P1)
{
    int t = blockIdx.x * blockDim.x + threadIdx.x;
    if (t >= 2048) return;
    int hp = t >> 9, f = t & 511;
    const float* wrow = W1 + (size_t)f * 512 + hp * 128;
    const float* as = a1s + hp * 128;
    const float* an = a1n + hp * 128;
    float s = 0.f, n = 0.f;
    #pragma unroll 4
    for (int d = 0; d < 128; d++) {
        float wv = wrow[d];
        s = fmaf(wv, as[d], s);
        n = fmaf(wv, an[d], n);
    }
    P1[t] = s;
    P1[2048 + t] = n;
}

__global__ void prepQ_kernel(const float* __restrict__ W0,
                             const float* __restrict__ P1,
                             float* __restrict__ Q)
{
    int t = blockIdx.x * blockDim.x + threadIdx.x;
    if (t >= 2048) return;
    int hp = t >> 9, i = t & 511;
    int h = i >> 7, k = i & 127;
    const float* wrow = W0 + (size_t)k * 512 + h * 128;
    const float* ps = P1 + hp * 512 + h * 128;
    const float* pn = P1 + 2048 + hp * 512 + h * 128;
    float s = 0.f, n = 0.f;
    #pragma unroll 4
    for (int d = 0; d < 128; d++) {
        float wv = wrow[d];
        s = fmaf(wv, ps[d], s);
        n = fmaf(wv, pn[d], n);
    }
    Q[t] = s;
    Q[2048 + t] = n;
}

// ---------------------------------------------------------------------------
// Attention + raw-row aggregation. One block (128 threads) per group.
//   xs: [G,F], xn: [G,E,F], Ws/Wn: [4,F], y: [G,4,F]
// Phase 1 (fused load+logit): warp w handles rows e = w, w+4, ... (row E =
//   self). lane = (head h=lane%4, sub s=lane/4); each quad broadcasts the
//   same global float4 chunks, FMAs against its head's weight slice, and
//   shfl_xor{4,8,16} reduces all 4 head logits simultaneously. h==0 lanes
//   mirror the row into smem (float4, conflict-free) for phase 3.
// Phase 2: softmax per head-warp over E lanes.
// Phase 3: y[h][f] = sum_e alpha[e,h]*xn[e][f], conflict-free scalar LDS.
// ---------------------------------------------------------------------------
template<int F, int E>
__global__ __launch_bounds__(128)
void attn_kernel(const float* __restrict__ xs,
                 const float* __restrict__ xn,
                 const float* __restrict__ Ws,
                 const float* __restrict__ Wn,
                 float* __restrict__ y)
{
    constexpr int FP = F + 4;          // padded row stride, rows stay 16B-aligned
    constexpr int CW = F / 8;          // columns per lane (per sub)
    const int g    = blockIdx.x;
    const int tid  = threadIdx.x;
    const int w    = tid >> 5;
    const int lane = tid & 31;
    const int h    = lane & 3;         // head
    const int s    = lane >> 2;        // sub 0..7

    __shared__ float sxn[E * FP];      // neighbor rows only
    __shared__ float slog[(E + 1) * 4];
    __shared__ float salpha[E * 4];

    const float* gxn = xn + (size_t)g * E * F;
    const float* gxs = xs + (size_t)g * F;

    // phase 1: rows e = w, w+4, ...  (e == E is the self row)
    for (int e = w; e <= E; e += 4) {
        const bool self = (e == E);
        const float* src = self ? gxs : (gxn + (size_t)e * F);
        const float* wp  = (self ? Ws : Wn) + h * F + s * CW;
        const float* xp  = src + s * CW;
        float acc = 0.f;
        #pragma unroll
        for (int j = 0; j < CW / 4; j++) {
            float4 xv = __ldg((const float4*)(xp + 4 * j));
            float4 wv = __ldg((const float4*)(wp + 4 * j));
            acc = fmaf(xv.x, wv.x, acc);
            acc = fmaf(xv.y, wv.y, acc);
            acc = fmaf(xv.z, wv.z, acc);
            acc = fmaf(xv.w, wv.w, acc);
            if (h == 0 && !self)
                *(float4*)&sxn[e * FP + s * CW + 4 * j] = xv;
        }
        acc += __shfl_xor_sync(0xffffffffu, acc, 4);
        acc += __shfl_xor_sync(0xffffffffu, acc, 8);
        acc += __shfl_xor_sync(0xffffffffu, acc, 16);
        if (lane < 4) slog[e * 4 + h] = acc;   // lane == h
    }
    __syncthreads();

    // phase 2: softmax over E per head (warp w = head)
    {
        float es = slog[E * 4 + w];
        float v;
        if (lane < E) {
            float l = es + slog[lane * 4 + w];
            v = (l >= 0.f) ? l : 0.2f * l;
        } else {
            v = -3.4e38f;
        }
        float m = v;
        #pragma unroll
        for (int o = 16; o; o >>= 1) m = fmaxf(m, __shfl_xor_sync(0xffffffffu, m, o));
        float p = (lane < E) ? __expf(v - m) : 0.f;
        float sum = p;
        #pragma unroll
        for (int o = 16; o; o >>= 1) sum += __shfl_xor_sync(0xffffffffu, sum, o);
        if (lane < E) salpha[lane * 4 + w] = p / sum;
    }
    __syncthreads();

    // phase 3: aggregate raw rows; thread tid covers columns {c*128+tid}
    constexpr int C = F / 128;
    float acc[C][4];
    #pragma unroll
    for (int c = 0; c < C; c++)
        #pragma unroll
        for (int hh = 0; hh < 4; hh++) acc[c][hh] = 0.f;

    for (int e = 0; e < E; e++) {
        float al[4];
        #pragma unroll
        for (int hh = 0; hh < 4; hh++) al[hh] = salpha[e * 4 + hh];
        #pragma unroll
        for (int c = 0; c < C; c++) {
            float val = sxn[e * FP + c * 128 + tid];
            #pragma unroll
            for (int hh = 0; hh < 4; hh++) acc[c][hh] = fmaf(al[hh], val, acc[c][hh]);
        }
    }
    float* gy = y + (size_t)g * (4 * F);
    #pragma unroll
    for (int hh = 0; hh < 4; hh++)
        #pragma unroll
        for (int c = 0; c < C; c++)
            gy[hh * F + c * 128 + tid] = acc[c][hh];
}

// ---------------------------------------------------------------------------
// fp32 tiled GEMM: C = A @ B. 64x64 tile, BK=16, 256 threads, 4x4/thread.
// ---------------------------------------------------------------------------
__global__ __launch_bounds__(256)
void gemm_kernel(const float* __restrict__ A, const float* __restrict__ B,
                 float* __restrict__ C,
                 int K, int lda, int ldb, int ldc,
                 int offA, int offB, int offC)
{
    A += (size_t)blockIdx.z * offA;
    B += (size_t)blockIdx.z * offB;
    C += (size_t)blockIdx.z * offC;

    const int row0 = blockIdx.y * 64;
    const int col0 = blockIdx.x * 64;
    const int tx = threadIdx.x;
    const int ty = threadIdx.y;
    const int tid = ty * 16 + tx;

    __shared__ float As[16][64];
    __shared__ float Bs[16][64];

    const int ar = tid >> 2;
    const int ac = (tid & 3) * 4;
    const int br = tid >> 4;
    const int bc = (tid & 15) * 4;

    float acc[4][4];
    #pragma unroll
    for (int i = 0; i < 4; i++)
        #pragma unroll
        for (int j = 0; j < 4; j++) acc[i][j] = 0.f;

    for (int k0 = 0; k0 < K; k0 += 16) {
        float4 av = *(const float4*)(A + (size_t)(row0 + ar) * lda + k0 + ac);
        As[ac + 0][ar] = av.x;
        As[ac + 1][ar] = av.y;
        As[ac + 2][ar] = av.z;
        As[ac + 3][ar] = av.w;
        float4 bv = *(const float4*)(B + (size_t)(k0 + br) * ldb + col0 + bc);
        *(float4*)&Bs[br][bc] = bv;
        __syncthreads();

        #pragma unroll
        for (int k = 0; k < 16; k++) {
            float4 a4 = *(const float4*)&As[k][ty * 4];
            float4 b4 = *(const float4*)&Bs[k][tx * 4];
            float a[4] = {a4.x, a4.y, a4.z, a4.w};
            float b[4] = {b4.x, b4.y, b4.z, b4.w};
            #pragma unroll
            for (int i = 0; i < 4; i++)
                #pragma unroll
                for (int j = 0; j < 4; j++)
                    acc[i][j] = fmaf(a[i], b[j], acc[i][j]);
        }
        __syncthreads();
    }

    #pragma unroll
    for (int i = 0; i < 4; i++) {
        float4 o = {acc[i][0], acc[i][1], acc[i][2], acc[i][3]};
        *(float4*)(C + (size_t)(row0 + ty * 4 + i) * ldc + col0 + tx * 4) = o;
    }
}

// ---------------------------------------------------------------------------
extern "C" void kernel_launch(void* const* d_in, const int* in_sizes, int n_in,
                              void* d_out, int out_size)
{
    const float* h0  = (const float*)d_in[0];
    const float* h1  = (const float*)d_in[1];
    const float* h2  = (const float*)d_in[2];
    const float* W0  = (const float*)d_in[3];
    const float* a0s = (const float*)d_in[4];
    const float* a0n = (const float*)d_in[5];
    const float* W1  = (const float*)d_in[6];
    const float* a1s = (const float*)d_in[7];
    const float* a1n = (const float*)d_in[8];
    const float* Wfc = (const float*)d_in[9];
    float* out = (float*)d_out;

    float* scr = nullptr;
    cudaGetSymbolAddress((void**)&scr, g_scratch);
    float* y1  = scr + OFF_Y1;
    float* y0  = scr + OFF_Y0;
    float* u   = scr + OFF_U;
    float* v   = scr + OFF_V;
    float* hs0 = scr + OFF_H;
    float* P0  = scr + OFF_P0;
    float* P1  = scr + OFF_P1;
    float* Q   = scr + OFF_Q;

    prep0_kernel<<<2, 256>>>(W0, a0s, a0n, P0);
    prep1_kernel<<<8, 256>>>(W1, a1s, a1n, P1);
    prepQ_kernel<<<8, 256>>>(W0, P1, Q);

    attn_kernel<128, 25><<<10240, 128>>>(h1, h2, P0, P0 + 512, y1);
    attn_kernel<128, 10><<<1024, 128>>>(h0, h1, P0, P0 + 512, y0);
    attn_kernel<512, 10><<<1024, 128>>>(y0, y1, Q, Q + 2048, u);

    gemm_kernel<<<dim3(2, 64, 4), dim3(16, 16)>>>(u, W0, v, 128, 512, 512, 512, 128, 128, 128);
    gemm_kernel<<<dim3(2, 16, 4), dim3(16, 16)>>>(v, W1, hs0, 512, 2048, 512, 512, 512, 128, 128);
    gemm_kernel<<<dim3(4, 16, 1), dim3(16, 16)>>>(hs0, Wfc, out, 512, 512, 256, 256, 0, 0, 0);
}

// round 4
// speedup vs baseline: 1.2751x; 1.2751x over previous
#include <cuda_runtime.h>
#include <cstdint>

// ---------------------------------------------------------------------------
// GAT hierarchical 2-layer, restructured (layer-1 W0-folding, see R2 notes).
// R4: attention kernel = (1) conflict-free smem fill, (2) register-resident
// weights dot phase reading L1-hot global x, (3) softmax + conflict-free
// aggregation. Fixes R3's per-row weight reloads (the L1=92% bottleneck).
// ---------------------------------------------------------------------------

// scratch layout (floats)
static constexpr size_t OFF_Y1 = 0;                        // [10240,512]
static constexpr size_t OFF_Y0 = OFF_Y1 + 10240ull * 512;  // [1024,512]
static constexpr size_t OFF_U  = OFF_Y0 + 1024ull * 512;   // [1024,2048]
static constexpr size_t OFF_V  = OFF_U  + 1024ull * 2048;  // [1024,2048]
static constexpr size_t OFF_H  = OFF_V  + 1024ull * 2048;  // [1024,512]
static constexpr size_t OFF_P0 = OFF_H  + 1024ull * 512;   // P0s[512],P0n[512]
static constexpr size_t OFF_P1 = OFF_P0 + 1024;            // P1s[2048],P1n[2048]
static constexpr size_t OFF_Q  = OFF_P1 + 4096;            // Qs[2048],Qn[2048]
static constexpr size_t SCRATCH_FLOATS = OFF_Q + 4096;

__device__ float g_scratch[SCRATCH_FLOATS];

static __device__ __forceinline__ float4 ldg4(const float* p) {
    return __ldg((const float4*)p);
}
static __device__ __forceinline__ float dot4(float4 a, float4 b, float acc) {
    acc = fmaf(a.x, b.x, acc);
    acc = fmaf(a.y, b.y, acc);
    acc = fmaf(a.z, b.z, acc);
    acc = fmaf(a.w, b.w, acc);
    return acc;
}

// ---------------------------------------------------------------------------
__global__ void prep0_kernel(const float* __restrict__ W0,
                             const float* __restrict__ a0s,
                             const float* __restrict__ a0n,
                             float* __restrict__ P0)
{
    int t = blockIdx.x * blockDim.x + threadIdx.x;
    if (t >= 512) return;
    int h = t >> 7, f = t & 127;
    const float* wrow = W0 + (size_t)f * 512 + h * 128;
    const float* as = a0s + h * 128;
    const float* an = a0n + h * 128;
    float s = 0.f, n = 0.f;
    #pragma unroll 4
    for (int d = 0; d < 128; d++) {
        float wv = wrow[d];
        s = fmaf(wv, as[d], s);
        n = fmaf(wv, an[d], n);
    }
    P0[t] = s;
    P0[512 + t] = n;
}

__global__ void prep1_kernel(const float* __restrict__ W1,
                             const float* __restrict__ a1s,
                             const float* __restrict__ a1n,
                             float* __restrict__ P1)
{
    int t = blockIdx.x * blockDim.x + threadIdx.x;
    if (t >= 2048) return;
    int hp = t >> 9, f = t & 511;
    const float* wrow = W1 + (size_t)f * 512 + hp * 128;
    const float* as = a1s + hp * 128;
    const float* an = a1n + hp * 128;
    float s = 0.f, n = 0.f;
    #pragma unroll 4
    for (int d = 0; d < 128; d++) {
        float wv = wrow[d];
        s = fmaf(wv, as[d], s);
        n = fmaf(wv, an[d], n);
    }
    P1[t] = s;
    P1[2048 + t] = n;
}

__global__ void prepQ_kernel(const float* __restrict__ W0,
                             const float* __restrict__ P1,
                             float* __restrict__ Q)
{
    int t = blockIdx.x * blockDim.x + threadIdx.x;
    if (t >= 2048) return;
    int hp = t >> 9, i = t & 511;
    int h = i >> 7, k = i & 127;
    const float* wrow = W0 + (size_t)k * 512 + h * 128;
    const float* ps = P1 + hp * 512 + h * 128;
    const float* pn = P1 + 2048 + hp * 512 + h * 128;
    float s = 0.f, n = 0.f;
    #pragma unroll 4
    for (int d = 0; d < 128; d++) {
        float wv = wrow[d];
        s = fmaf(wv, ps[d], s);
        n = fmaf(wv, pn[d], n);
    }
    Q[t] = s;
    Q[2048 + t] = n;
}

// ---------------------------------------------------------------------------
// Attention + raw-row aggregation. One block (128 threads) per group.
// ---------------------------------------------------------------------------
template<int F, int E>
__global__ __launch_bounds__(128)
void attn_kernel(const float* __restrict__ xs,
                 const float* __restrict__ xn,
                 const float* __restrict__ Ws,
                 const float* __restrict__ Wn,
                 float* __restrict__ y)
{
    constexpr int FP = F + 4;
    const int g    = blockIdx.x;
    const int tid  = threadIdx.x;
    const int w    = tid >> 5;
    const int lane = tid & 31;

    __shared__ float sxn[E * FP];
    __shared__ float slog[(E + 1) * 4];
    __shared__ float salpha[E * 4];

    const float* gxn = xn + (size_t)g * E * F;
    const float* gxs = xs + (size_t)g * F;

    // phase 0: fill smem with neighbor rows (conflict-free float4 stores)
    {
        const float4* gxn4 = (const float4*)gxn;
        constexpr int NV = E * (F / 4);
        for (int i = tid; i < NV; i += 128) {
            int e = i / (F / 4);
            int k = i - e * (F / 4);
            *(float4*)&sxn[e * FP + 4 * k] = gxn4[i];
        }
    }

    // phase 1: logits. x re-read from global (L1-hot), weights in registers.
    if constexpr (F == 128) {
        // quad scheme: lane = (head h, sub s); 3-shfl reduce over 8 subs.
        const int h = lane & 3;
        const int s = lane >> 2;
        const float* wb = Wn + h * 128 + s * 16;
        float4 w0 = ldg4(wb), w1 = ldg4(wb + 4), w2 = ldg4(wb + 8), w3 = ldg4(wb + 12);

        for (int e = w; e < E; e += 4) {
            const float* xp = gxn + e * 128 + s * 16;
            float acc = 0.f;
            acc = dot4(ldg4(xp),      w0, acc);
            acc = dot4(ldg4(xp + 4),  w1, acc);
            acc = dot4(ldg4(xp + 8),  w2, acc);
            acc = dot4(ldg4(xp + 12), w3, acc);
            acc += __shfl_xor_sync(0xffffffffu, acc, 4);
            acc += __shfl_xor_sync(0xffffffffu, acc, 8);
            acc += __shfl_xor_sync(0xffffffffu, acc, 16);
            if (lane < 4) slog[e * 4 + lane] = acc;
        }
        if (w == 0) {  // self row
            const float* sb = Ws + h * 128 + s * 16;
            const float* xp = gxs + s * 16;
            float acc = 0.f;
            acc = dot4(ldg4(xp),      ldg4(sb),      acc);
            acc = dot4(ldg4(xp + 4),  ldg4(sb + 4),  acc);
            acc = dot4(ldg4(xp + 8),  ldg4(sb + 8),  acc);
            acc = dot4(ldg4(xp + 12), ldg4(sb + 12), acc);
            acc += __shfl_xor_sync(0xffffffffu, acc, 4);
            acc += __shfl_xor_sync(0xffffffffu, acc, 8);
            acc += __shfl_xor_sync(0xffffffffu, acc, 16);
            if (lane < 4) slog[E * 4 + lane] = acc;
        }
    } else {
        // F == 512: warp-per-head, weights in 16 regs/lane, 5-shfl reduce.
        const float* wb = Wn + w * 512 + lane * 16;
        float4 w0 = ldg4(wb), w1 = ldg4(wb + 4), w2 = ldg4(wb + 8), w3 = ldg4(wb + 12);

        for (int e = 0; e < E; e++) {
            const float* xp = gxn + (size_t)e * 512 + lane * 16;
            float acc = 0.f;
            acc = dot4(ldg4(xp),      w0, acc);
            acc = dot4(ldg4(xp + 4),  w1, acc);
            acc = dot4(ldg4(xp + 8),  w2, acc);
            acc = dot4(ldg4(xp + 12), w3, acc);
            #pragma unroll
            for (int o = 16; o; o >>= 1) acc += __shfl_xor_sync(0xffffffffu, acc, o);
            if (lane == 0) slog[e * 4 + w] = acc;
        }
        {   // self row
            const float* sb = Ws + w * 512 + lane * 16;
            const float* xp = gxs + lane * 16;
            float acc = 0.f;
            acc = dot4(ldg4(xp),      ldg4(sb),      acc);
            acc = dot4(ldg4(xp + 4),  ldg4(sb + 4),  acc);
            acc = dot4(ldg4(xp + 8),  ldg4(sb + 8),  acc);
            acc = dot4(ldg4(xp + 12), ldg4(sb + 12), acc);
            #pragma unroll
            for (int o = 16; o; o >>= 1) acc += __shfl_xor_sync(0xffffffffu, acc, o);
            if (lane == 0) slog[E * 4 + w] = acc;
        }
    }
    __syncthreads();

    // phase 2: softmax over E per head (warp w = head)
    {
        float es = slog[E * 4 + w];
        float v;
        if (lane < E) {
            float l = es + slog[lane * 4 + w];
            v = (l >= 0.f) ? l : 0.2f * l;
        } else {
            v = -3.4e38f;
        }
        float m = v;
        #pragma unroll
        for (int o = 16; o; o >>= 1) m = fmaxf(m, __shfl_xor_sync(0xffffffffu, m, o));
        float p = (lane < E) ? __expf(v - m) : 0.f;
        float sum = p;
        #pragma unroll
        for (int o = 16; o; o >>= 1) sum += __shfl_xor_sync(0xffffffffu, sum, o);
        if (lane < E) salpha[lane * 4 + w] = p / sum;
    }
    __syncthreads();

    // phase 3: aggregate raw rows; thread tid covers columns {c*128+tid}
    constexpr int C = F / 128;
    float acc[C][4];
    #pragma unroll
    for (int c = 0; c < C; c++)
        #pragma unroll
        for (int hh = 0; hh < 4; hh++) acc[c][hh] = 0.f;

    for (int e = 0; e < E; e++) {
        float al[4];
        #pragma unroll
        for (int hh = 0; hh < 4; hh++) al[hh] = salpha[e * 4 + hh];
        #pragma unroll
        for (int c = 0; c < C; c++) {
            float val = sxn[e * FP + c * 128 + tid];
            #pragma unroll
            for (int hh = 0; hh < 4; hh++) acc[c][hh] = fmaf(al[hh], val, acc[c][hh]);
        }
    }
    float* gy = y + (size_t)g * (4 * F);
    #pragma unroll
    for (int hh = 0; hh < 4; hh++)
        #pragma unroll
        for (int c = 0; c < C; c++)
            gy[hh * F + c * 128 + tid] = acc[c][hh];
}

// ---------------------------------------------------------------------------
// fp32 tiled GEMM: C = A @ B. 64x64 tile, BK=16, 256 threads, 4x4/thread.
// ---------------------------------------------------------------------------
__global__ __launch_bounds__(256)
void gemm_kernel(const float* __restrict__ A, const float* __restrict__ B,
                 float* __restrict__ C,
                 int K, int lda, int ldb, int ldc,
                 int offA, int offB, int offC)
{
    A += (size_t)blockIdx.z * offA;
    B += (size_t)blockIdx.z * offB;
    C += (size_t)blockIdx.z * offC;

    const int row0 = blockIdx.y * 64;
    const int col0 = blockIdx.x * 64;
    const int tx = threadIdx.x;
    const int ty = threadIdx.y;
    const int tid = ty * 16 + tx;

    __shared__ float As[16][64];
    __shared__ float Bs[16][64];

    const int ar = tid >> 2;
    const int ac = (tid & 3) * 4;
    const int br = tid >> 4;
    const int bc = (tid & 15) * 4;

    float acc[4][4];
    #pragma unroll
    for (int i = 0; i < 4; i++)
        #pragma unroll
        for (int j = 0; j < 4; j++) acc[i][j] = 0.f;

    for (int k0 = 0; k0 < K; k0 += 16) {
        float4 av = *(const float4*)(A + (size_t)(row0 + ar) * lda + k0 + ac);
        As[ac + 0][ar] = av.x;
        As[ac + 1][ar] = av.y;
        As[ac + 2][ar] = av.z;
        As[ac + 3][ar] = av.w;
        float4 bv = *(const float4*)(B + (size_t)(k0 + br) * ldb + col0 + bc);
        *(float4*)&Bs[br][bc] = bv;
        __syncthreads();

        #pragma unroll
        for (int k = 0; k < 16; k++) {
            float4 a4 = *(const float4*)&As[k][ty * 4];
            float4 b4 = *(const float4*)&Bs[k][tx * 4];
            float a[4] = {a4.x, a4.y, a4.z, a4.w};
            float b[4] = {b4.x, b4.y, b4.z, b4.w};
            #pragma unroll
            for (int i = 0; i < 4; i++)
                #pragma unroll
                for (int j = 0; j < 4; j++)
                    acc[i][j] = fmaf(a[i], b[j], acc[i][j]);
        }
        __syncthreads();
    }

    #pragma unroll
    for (int i = 0; i < 4; i++) {
        float4 o = {acc[i][0], acc[i][1], acc[i][2], acc[i][3]};
        *(float4*)(C + (size_t)(row0 + ty * 4 + i) * ldc + col0 + tx * 4) = o;
    }
}

// ---------------------------------------------------------------------------
extern "C" void kernel_launch(void* const* d_in, const int* in_sizes, int n_in,
                              void* d_out, int out_size)
{
    const float* h0  = (const float*)d_in[0];
    const float* h1  = (const float*)d_in[1];
    const float* h2  = (const float*)d_in[2];
    const float* W0  = (const float*)d_in[3];
    const float* a0s = (const float*)d_in[4];
    const float* a0n = (const float*)d_in[5];
    const float* W1  = (const float*)d_in[6];
    const float* a1s = (const float*)d_in[7];
    const float* a1n = (const float*)d_in[8];
    const float* Wfc = (const float*)d_in[9];
    float* out = (float*)d_out;

    float* scr = nullptr;
    cudaGetSymbolAddress((void**)&scr, g_scratch);
    float* y1  = scr + OFF_Y1;
    float* y0  = scr + OFF_Y0;
    float* u   = scr + OFF_U;
    float* v   = scr + OFF_V;
    float* hs0 = scr + OFF_H;
    float* P0  = scr + OFF_P0;
    float* P1  = scr + OFF_P1;
    float* Q   = scr + OFF_Q;

    prep0_kernel<<<2, 256>>>(W0, a0s, a0n, P0);
    prep1_kernel<<<8, 256>>>(W1, a1s, a1n, P1);
    prepQ_kernel<<<8, 256>>>(W0, P1, Q);

    attn_kernel<128, 25><<<10240, 128>>>(h1, h2, P0, P0 + 512, y1);
    attn_kernel<128, 10><<<1024, 128>>>(h0, h1, P0, P0 + 512, y0);
    attn_kernel<512, 10><<<1024, 128>>>(y0, y1, Q, Q + 2048, u);

    gemm_kernel<<<dim3(2, 64, 4), dim3(16, 16)>>>(u, W0, v, 128, 512, 512, 512, 128, 128, 128);
    gemm_kernel<<<dim3(2, 16, 4), dim3(16, 16)>>>(v, W1, hs0, 512, 2048, 512, 512, 512, 128, 128);
    gemm_kernel<<<dim3(4, 16, 1), dim3(16, 16)>>>(hs0, Wfc, out, 512, 512, 256, 256, 0, 0, 0);
}

// round 5
// speedup vs baseline: 1.6045x; 1.2583x over previous
#include <cuda_runtime.h>
#include <cstdint>

// ---------------------------------------------------------------------------
// GAT hierarchical 2-layer. R5: TMA (cp.async.bulk) smem fill for attention
// (removes LDG+STS l1tex transits), truly conflict-free LDS patterns, fused
// F=128 attention launch, and W0/W1 folded into one GEMM via N = W0blk @ W1.
// ---------------------------------------------------------------------------

// scratch layout (floats)
static constexpr size_t OFF_Y1 = 0;                        // [10240,512]
static constexpr size_t OFF_Y0 = OFF_Y1 + 10240ull * 512;  // [1024,512]
static constexpr size_t OFF_U  = OFF_Y0 + 1024ull * 512;   // [1024,2048]
static constexpr size_t OFF_H  = OFF_U  + 1024ull * 2048;  // [1024,512]
static constexpr size_t OFF_P0 = OFF_H  + 1024ull * 512;   // P0s[512],P0n[512]
static constexpr size_t OFF_P1 = OFF_P0 + 1024;            // P1s[2048],P1n[2048]
static constexpr size_t OFF_Q  = OFF_P1 + 4096;            // Qs[2048],Qn[2048]
static constexpr size_t OFF_N  = OFF_Q  + 4096;            // N[4][512][128]
static constexpr size_t SCRATCH_FLOATS = OFF_N + 4ull * 512 * 128;

__device__ float g_scratch[SCRATCH_FLOATS];

static __device__ __forceinline__ float4 ldg4(const float* p) {
    return __ldg((const float4*)p);
}
static __device__ __forceinline__ float dot4(float4 a, float4 b, float acc) {
    acc = fmaf(a.x, b.x, acc);
    acc = fmaf(a.y, b.y, acc);
    acc = fmaf(a.z, b.z, acc);
    acc = fmaf(a.w, b.w, acc);
    return acc;
}
static __device__ __forceinline__ uint32_t smem_u32(const void* p) {
    return (uint32_t)__cvta_generic_to_shared(p);
}
static __device__ __forceinline__ void mbar_init(uint32_t mbar, uint32_t cnt) {
    asm volatile("mbarrier.init.shared.b64 [%0], %1;" :: "r"(mbar), "r"(cnt) : "memory");
}
static __device__ __forceinline__ void mbar_expect_tx(uint32_t mbar, uint32_t bytes) {
    asm volatile("mbarrier.arrive.expect_tx.shared.b64 _, [%0], %1;"
                 :: "r"(mbar), "r"(bytes) : "memory");
}
static __device__ __forceinline__ void bulk_g2s(uint32_t dst, const void* src,
                                                uint32_t bytes, uint32_t mbar) {
    asm volatile("cp.async.bulk.shared::cluster.global.mbarrier::complete_tx::bytes "
                 "[%0], [%1], %2, [%3];"
                 :: "r"(dst), "l"(src), "r"(bytes), "r"(mbar) : "memory");
}
static __device__ __forceinline__ void mbar_wait(uint32_t mbar, uint32_t parity) {
    asm volatile(
        "{\n\t.reg .pred P;\n"
        "W_%=:\n\t"
        "mbarrier.try_wait.parity.shared.b64 P, [%0], %1;\n\t"
        "@P bra D_%=;\n\t"
        "bra W_%=;\n"
        "D_%=:\n\t}"
        :: "r"(mbar), "r"(parity) : "memory");
}
static __device__ __forceinline__ float4 lds4(const float* p) {
    float4 v;
    asm volatile("ld.shared.v4.f32 {%0,%1,%2,%3}, [%4];"
                 : "=f"(v.x), "=f"(v.y), "=f"(v.z), "=f"(v.w)
                 : "r"(smem_u32(p)));
    return v;
}

// ---------------------------------------------------------------------------
__global__ void prep0_kernel(const float* __restrict__ W0,
                             const float* __restrict__ a0s,
                             const float* __restrict__ a0n,
                             float* __restrict__ P0)
{
    int t = blockIdx.x * blockDim.x + threadIdx.x;
    if (t >= 512) return;
    int h = t >> 7, f = t & 127;
    const float* wrow = W0 + (size_t)f * 512 + h * 128;
    const float* as = a0s + h * 128;
    const float* an = a0n + h * 128;
    float s = 0.f, n = 0.f;
    #pragma unroll 4
    for (int d = 0; d < 128; d++) {
        float wv = wrow[d];
        s = fmaf(wv, as[d], s);
        n = fmaf(wv, an[d], n);
    }
    P0[t] = s;
    P0[512 + t] = n;
}

__global__ void prep1_kernel(const float* __restrict__ W1,
                             const float* __restrict__ a1s,
                             const float* __restrict__ a1n,
                             float* __restrict__ P1)
{
    int t = blockIdx.x * blockDim.x + threadIdx.x;
    if (t >= 2048) return;
    int hp = t >> 9, f = t & 511;
    const float* wrow = W1 + (size_t)f * 512 + hp * 128;
    const float* as = a1s + hp * 128;
    const float* an = a1n + hp * 128;
    float s = 0.f, n = 0.f;
    #pragma unroll 4
    for (int d = 0; d < 128; d++) {
        float wv = wrow[d];
        s = fmaf(wv, as[d], s);
        n = fmaf(wv, an[d], n);
    }
    P1[t] = s;
    P1[2048 + t] = n;
}

__global__ void prepQ_kernel(const float* __restrict__ W0,
                             const float* __restrict__ P1,
                             float* __restrict__ Q)
{
    int t = blockIdx.x * blockDim.x + threadIdx.x;
    if (t >= 2048) return;
    int hp = t >> 9, i = t & 511;
    int h = i >> 7, k = i & 127;
    const float* wrow = W0 + (size_t)k * 512 + h * 128;
    const float* ps = P1 + hp * 512 + h * 128;
    const float* pn = P1 + 2048 + hp * 512 + h * 128;
    float s = 0.f, n = 0.f;
    #pragma unroll 4
    for (int d = 0; d < 128; d++) {
        float wv = wrow[d];
        s = fmaf(wv, ps[d], s);
        n = fmaf(wv, pn[d], n);
    }
    Q[t] = s;
    Q[2048 + t] = n;
}

// ---------------------------------------------------------------------------
// shared GEMM body: C = A@B, 64x64 tile, BK=16, 256 threads (16x16)
// ---------------------------------------------------------------------------
static __device__ __forceinline__ void gemm_body(
    const float* __restrict__ A, const float* __restrict__ B,
    float* __restrict__ C, int K, int lda, int ldb, int ldc)
{
    const int row0 = blockIdx.y * 64;
    const int col0 = blockIdx.x * 64;
    const int tx = threadIdx.x;
    const int ty = threadIdx.y;
    const int tid = ty * 16 + tx;

    __shared__ float As[16][64];
    __shared__ float Bs[16][64];

    const int ar = tid >> 2;
    const int ac = (tid & 3) * 4;
    const int br = tid >> 4;
    const int bc = (tid & 15) * 4;

    float acc[4][4];
    #pragma unroll
    for (int i = 0; i < 4; i++)
        #pragma unroll
        for (int j = 0; j < 4; j++) acc[i][j] = 0.f;

    for (int k0 = 0; k0 < K; k0 += 16) {
        float4 av = *(const float4*)(A + (size_t)(row0 + ar) * lda + k0 + ac);
        As[ac + 0][ar] = av.x;
        As[ac + 1][ar] = av.y;
        As[ac + 2][ar] = av.z;
        As[ac + 3][ar] = av.w;
        float4 bv = *(const float4*)(B + (size_t)(k0 + br) * ldb + col0 + bc);
        *(float4*)&Bs[br][bc] = bv;
        __syncthreads();

        #pragma unroll
        for (int k = 0; k < 16; k++) {
            float4 a4 = *(const float4*)&As[k][ty * 4];
            float4 b4 = *(const float4*)&Bs[k][tx * 4];
            float a[4] = {a4.x, a4.y, a4.z, a4.w};
            float b[4] = {b4.x, b4.y, b4.z, b4.w};
            #pragma unroll
            for (int i = 0; i < 4; i++)
                #pragma unroll
                for (int j = 0; j < 4; j++)
                    acc[i][j] = fmaf(a[i], b[j], acc[i][j]);
        }
        __syncthreads();
    }

    #pragma unroll
    for (int i = 0; i < 4; i++) {
        float4 o = {acc[i][0], acc[i][1], acc[i][2], acc[i][3]};
        *(float4*)(C + (size_t)(row0 + ty * 4 + i) * ldc + col0 + tx * 4) = o;
    }
}

__global__ __launch_bounds__(256)
void gemm_kernel(const float* __restrict__ A, const float* __restrict__ B,
                 float* __restrict__ C,
                 int K, int lda, int ldb, int ldc,
                 int offA, int offB, int offC)
{
    gemm_body(A + (size_t)blockIdx.z * offA, B + (size_t)blockIdx.z * offB,
              C + (size_t)blockIdx.z * offC, K, lda, ldb, ldc);
}

// N[hp][h*128+k][d'] = sum_d W0[k, h*128+d] * W1[h*128+d, hp*128+d']
__global__ __launch_bounds__(256)
void prepN_kernel(const float* __restrict__ W0, const float* __restrict__ W1,
                  float* __restrict__ Nmat)
{
    int z = blockIdx.z;
    int hp = z >> 2, h = z & 3;
    const float* A = W0 + h * 128;                              // lda 512
    const float* B = W1 + (size_t)(h * 128) * 512 + hp * 128;   // ldb 512
    float* C = Nmat + (size_t)hp * 65536 + (size_t)(h * 128) * 128; // ldc 128
    gemm_body(A, B, C, 128, 512, 512, 128);
}

// ---------------------------------------------------------------------------
// F=128 attention, both levels fused. Blocks [0,G1): (h1,h2,E=25)->y1;
// blocks [G1,G1+G2): (h0,h1,E=10)->y0.
// TMA fills smem; logits via conflict-free LDS.128 with register weights.
// ---------------------------------------------------------------------------
__global__ __launch_bounds__(128)
void attn128_kernel(const float* __restrict__ h0, const float* __restrict__ h1,
                    const float* __restrict__ h2,
                    const float* __restrict__ Ws, const float* __restrict__ Wn,
                    float* __restrict__ y1, float* __restrict__ y0, int G1)
{
    __shared__ float sxn[25 * 128];
    __shared__ float slog[26 * 4];
    __shared__ float salpha[25 * 4];
    __shared__ uint64_t mbar_s;

    const int b = blockIdx.x;
    const bool big = b < G1;
    const int g = big ? b : b - G1;
    const int E = big ? 25 : 10;
    const float* gxn = big ? (h2 + (size_t)g * 25 * 128) : (h1 + (size_t)g * 10 * 128);
    const float* gxs = big ? (h1 + (size_t)g * 128) : (h0 + (size_t)g * 128);
    float* gy = (big ? y1 : y0) + (size_t)g * 512;

    const int tid  = threadIdx.x;
    const int w    = tid >> 5;
    const int lane = tid & 31;
    const uint32_t mbar = smem_u32(&mbar_s);

    if (tid == 0) {
        mbar_init(mbar, 1);
        asm volatile("fence.proxy.async.shared::cta;" ::: "memory");
    }
    __syncthreads();
    if (tid == 0) {
        mbar_expect_tx(mbar, (uint32_t)(E * 128 * 4));
        bulk_g2s(smem_u32(sxn), gxn, (uint32_t)(E * 128 * 4), mbar);
    }

    // weights into registers while TMA is in flight.
    // lane = (head hh = lane&3, sub s = lane>>2); chunk j covers float cols
    // 4*(s + 8j)..+3  -> LDS.128 hits 8 distinct bank-groups (conflict-free).
    const int hh = lane & 3;
    const int s  = lane >> 2;
    float4 wq[4];
    #pragma unroll
    for (int j = 0; j < 4; j++) wq[j] = ldg4(Wn + hh * 128 + 4 * (s + 8 * j));

    // self logit (warp 0): read self row from global, same quad reduction.
    if (w == 0) {
        float acc = 0.f;
        #pragma unroll
        for (int j = 0; j < 4; j++)
            acc = dot4(ldg4(gxs + 4 * (s + 8 * j)),
                       ldg4(Ws + hh * 128 + 4 * (s + 8 * j)), acc);
        acc += __shfl_xor_sync(0xffffffffu, acc, 4);
        acc += __shfl_xor_sync(0xffffffffu, acc, 8);
        acc += __shfl_xor_sync(0xffffffffu, acc, 16);
        if (lane < 4) slog[E * 4 + lane] = acc;
    }

    mbar_wait(mbar, 0);

    // neighbor logits from smem (conflict-free LDS.128)
    for (int e = w; e < E; e += 4) {
        const float* xp = &sxn[e * 128];
        float acc = 0.f;
        #pragma unroll
        for (int j = 0; j < 4; j++)
            acc = dot4(lds4(xp + 4 * (s + 8 * j)), wq[j], acc);
        acc += __shfl_xor_sync(0xffffffffu, acc, 4);
        acc += __shfl_xor_sync(0xffffffffu, acc, 8);
        acc += __shfl_xor_sync(0xffffffffu, acc, 16);
        if (lane < 4) slog[e * 4 + lane] = acc;
    }
    __syncthreads();

    // softmax over E per head (warp w = head)
    {
        float es = slog[E * 4 + w];
        float v;
        if (lane < E) {
            float l = es + slog[lane * 4 + w];
            v = (l >= 0.f) ? l : 0.2f * l;
        } else {
            v = -3.4e38f;
        }
        float m = v;
        #pragma unroll
        for (int o = 16; o; o >>= 1) m = fmaxf(m, __shfl_xor_sync(0xffffffffu, m, o));
        float p = (lane < E) ? __expf(v - m) : 0.f;
        float sum = p;
        #pragma unroll
        for (int o = 16; o; o >>= 1) sum += __shfl_xor_sync(0xffffffffu, sum, o);
        if (lane < E) salpha[lane * 4 + w] = p / sum;
    }
    __syncthreads();

    // aggregate: thread tid covers column tid; conflict-free scalar LDS
    float acc[4] = {0.f, 0.f, 0.f, 0.f};
    for (int e = 0; e < E; e++) {
        float val = sxn[e * 128 + tid];
        #pragma unroll
        for (int q = 0; q < 4; q++) acc[q] = fmaf(salpha[e * 4 + q], val, acc[q]);
    }
    #pragma unroll
    for (int q = 0; q < 4; q++) gy[q * 128 + tid] = acc[q];
}

// ---------------------------------------------------------------------------
// F=512, E=10 attention (layer 1): xs=y0, xn=y1(rows), weights Q. -> u
// ---------------------------------------------------------------------------
__global__ __launch_bounds__(128)
void attn512_kernel(const float* __restrict__ xs, const float* __restrict__ xn,
                    const float* __restrict__ Ws, const float* __restrict__ Wn,
                    float* __restrict__ y)
{
    constexpr int E = 10, F = 512;
    __shared__ float sxn[E * F];
    __shared__ float slog[(E + 1) * 4];
    __shared__ float salpha[E * 4];
    __shared__ uint64_t mbar_s;

    const int g    = blockIdx.x;
    const int tid  = threadIdx.x;
    const int w    = tid >> 5;
    const int lane = tid & 31;
    const uint32_t mbar = smem_u32(&mbar_s);
    const float* gxn = xn + (size_t)g * E * F;
    const float* gxs = xs + (size_t)g * F;

    if (tid == 0) {
        mbar_init(mbar, 1);
        asm volatile("fence.proxy.async.shared::cta;" ::: "memory");
    }
    __syncthreads();
    if (tid == 0) {
        mbar_expect_tx(mbar, E * F * 4);
        bulk_g2s(smem_u32(sxn), gxn, E * F * 4, mbar);
    }

    // warp-per-head; lane reads chunks at float cols 4*(lane + 32j), j=0..3
    float4 wq[4];
    #pragma unroll
    for (int j = 0; j < 4; j++) wq[j] = ldg4(Wn + w * F + 4 * (lane + 32 * j));

    {   // self logit from global
        float acc = 0.f;
        #pragma unroll
        for (int j = 0; j < 4; j++)
            acc = dot4(ldg4(gxs + 4 * (lane + 32 * j)),
                       ldg4(Ws + w * F + 4 * (lane + 32 * j)), acc);
        #pragma unroll
        for (int o = 16; o; o >>= 1) acc += __shfl_xor_sync(0xffffffffu, acc, o);
        if (lane == 0) slog[E * 4 + w] = acc;
    }

    mbar_wait(mbar, 0);

    for (int e = 0; e < E; e++) {
        const float* xp = &sxn[e * F];
        float acc = 0.f;
        #pragma unroll
        for (int j = 0; j < 4; j++)
            acc = dot4(lds4(xp + 4 * (lane + 32 * j)), wq[j], acc);
        #pragma unroll
        for (int o = 16; o; o >>= 1) acc += __shfl_xor_sync(0xffffffffu, acc, o);
        if (lane == 0) slog[e * 4 + w] = acc;
    }
    __syncthreads();

    {   // softmax
        float es = slog[E * 4 + w];
        float v;
        if (lane < E) {
            float l = es + slog[lane * 4 + w];
            v = (l >= 0.f) ? l : 0.2f * l;
        } else {
            v = -3.4e38f;
        }
        float m = v;
        #pragma unroll
        for (int o = 16; o; o >>= 1) m = fmaxf(m, __shfl_xor_sync(0xffffffffu, m, o));
        float p = (lane < E) ? __expf(v - m) : 0.f;
        float sum = p;
        #pragma unroll
        for (int o = 16; o; o >>= 1) sum += __shfl_xor_sync(0xffffffffu, sum, o);
        if (lane < E) salpha[lane * 4 + w] = p / sum;
    }
    __syncthreads();

    // aggregate: thread tid covers columns c*128+tid, c=0..3
    float acc[4][4];
    #pragma unroll
    for (int c = 0; c < 4; c++)
        #pragma unroll
        for (int q = 0; q < 4; q++) acc[c][q] = 0.f;
    for (int e = 0; e < E; e++) {
        float al[4];
        #pragma unroll
        for (int q = 0; q < 4; q++) al[q] = salpha[e * 4 + q];
        #pragma unroll
        for (int c = 0; c < 4; c++) {
            float val = sxn[e * F + c * 128 + tid];
            #pragma unroll
            for (int q = 0; q < 4; q++) acc[c][q] = fmaf(al[q], val, acc[c][q]);
        }
    }
    float* gy = y + (size_t)g * (4 * F);
    #pragma unroll
    for (int q = 0; q < 4; q++)
        #pragma unroll
        for (int c = 0; c < 4; c++)
            gy[q * F + c * 128 + tid] = acc[c][q];
}

// ---------------------------------------------------------------------------
extern "C" void kernel_launch(void* const* d_in, const int* in_sizes, int n_in,
                              void* d_out, int out_size)
{
    const float* h0  = (const float*)d_in[0];
    const float* h1  = (const float*)d_in[1];
    const float* h2  = (const float*)d_in[2];
    const float* W0  = (const float*)d_in[3];
    const float* a0s = (const float*)d_in[4];
    const float* a0n = (const float*)d_in[5];
    const float* W1  = (const float*)d_in[6];
    const float* a1s = (const float*)d_in[7];
    const float* a1n = (const float*)d_in[8];
    const float* Wfc = (const float*)d_in[9];
    float* out = (float*)d_out;

    float* scr = nullptr;
    cudaGetSymbolAddress((void**)&scr, g_scratch);
    float* y1   = scr + OFF_Y1;
    float* y0   = scr + OFF_Y0;
    float* u    = scr + OFF_U;
    float* hs0  = scr + OFF_H;
    float* P0   = scr + OFF_P0;
    float* P1   = scr + OFF_P1;
    float* Q    = scr + OFF_Q;
    float* Nmat = scr + OFF_N;

    prep0_kernel<<<2, 256>>>(W0, a0s, a0n, P0);
    prep1_kernel<<<8, 256>>>(W1, a1s, a1n, P1);
    prepQ_kernel<<<8, 256>>>(W0, P1, Q);
    prepN_kernel<<<dim3(2, 2, 16), dim3(16, 16)>>>(W0, W1, Nmat);

    // both F=128 attentions in one launch
    attn128_kernel<<<10240 + 1024, 128>>>(h0, h1, h2, P0, P0 + 512, y1, y0, 10240);

    // layer-1 attention -> u [1024, 4(h'), 512]
    attn512_kernel<<<1024, 128>>>(y0, y1, Q, Q + 2048, u);

    // hs0[g, hp*128+d'] = u[g,hp,:] @ N[hp]   (per-hp batched)
    gemm_kernel<<<dim3(2, 16, 4), dim3(16, 16)>>>(u, Nmat, hs0, 512, 2048, 128, 512,
                                                  512, 512 * 128, 128);
    // out = hs0 @ Wfc
    gemm_kernel<<<dim3(4, 16, 1), dim3(16, 16)>>>(hs0, Wfc, out, 512, 512, 256, 256,
                                                  0, 0, 0);
}

// round 6
// speedup vs baseline: 2.4486x; 1.5261x over previous
#include <cuda_runtime.h>
#include <cstdint>

// ---------------------------------------------------------------------------
// GAT hierarchical 2-layer. R6: prepN re-tiled 32x32 (4x parallelism),
// prep1/prepQ replaced by Q = N @ a1 (exact), prep0 folded into same kernel,
// GEMMs get register double-buffering. Attention kernels unchanged from R5.
// ---------------------------------------------------------------------------

// scratch layout (floats)
static constexpr size_t OFF_Y1 = 0;                        // [10240,512]
static constexpr size_t OFF_Y0 = OFF_Y1 + 10240ull * 512;  // [1024,512]
static constexpr size_t OFF_U  = OFF_Y0 + 1024ull * 512;   // [1024,2048]
static constexpr size_t OFF_H  = OFF_U  + 1024ull * 2048;  // [1024,512]
static constexpr size_t OFF_P0 = OFF_H  + 1024ull * 512;   // P0s[512],P0n[512]
static constexpr size_t OFF_Q  = OFF_P0 + 1024;            // Qs[2048],Qn[2048]
static constexpr size_t OFF_N  = OFF_Q  + 4096;            // N[4][512][128]
static constexpr size_t SCRATCH_FLOATS = OFF_N + 4ull * 512 * 128;

__device__ float g_scratch[SCRATCH_FLOATS];

static __device__ __forceinline__ float4 ldg4(const float* p) {
    return __ldg((const float4*)p);
}
static __device__ __forceinline__ float dot4(float4 a, float4 b, float acc) {
    acc = fmaf(a.x, b.x, acc);
    acc = fmaf(a.y, b.y, acc);
    acc = fmaf(a.z, b.z, acc);
    acc = fmaf(a.w, b.w, acc);
    return acc;
}
static __device__ __forceinline__ uint32_t smem_u32(const void* p) {
    return (uint32_t)__cvta_generic_to_shared(p);
}
static __device__ __forceinline__ void mbar_init(uint32_t mbar, uint32_t cnt) {
    asm volatile("mbarrier.init.shared.b64 [%0], %1;" :: "r"(mbar), "r"(cnt) : "memory");
}
static __device__ __forceinline__ void mbar_expect_tx(uint32_t mbar, uint32_t bytes) {
    asm volatile("mbarrier.arrive.expect_tx.shared.b64 _, [%0], %1;"
                 :: "r"(mbar), "r"(bytes) : "memory");
}
static __device__ __forceinline__ void bulk_g2s(uint32_t dst, const void* src,
                                                uint32_t bytes, uint32_t mbar) {
    asm volatile("cp.async.bulk.shared::cluster.global.mbarrier::complete_tx::bytes "
                 "[%0], [%1], %2, [%3];"
                 :: "r"(dst), "l"(src), "r"(bytes), "r"(mbar) : "memory");
}
static __device__ __forceinline__ void mbar_wait(uint32_t mbar, uint32_t parity) {
    asm volatile(
        "{\n\t.reg .pred P;\n"
        "W_%=:\n\t"
        "mbarrier.try_wait.parity.shared.b64 P, [%0], %1;\n\t"
        "@P bra D_%=;\n\t"
        "bra W_%=;\n"
        "D_%=:\n\t}"
        :: "r"(mbar), "r"(parity) : "memory");
}
static __device__ __forceinline__ float4 lds4(const float* p) {
    float4 v;
    asm volatile("ld.shared.v4.f32 {%0,%1,%2,%3}, [%4];"
                 : "=f"(v.x), "=f"(v.y), "=f"(v.z), "=f"(v.w)
                 : "r"(smem_u32(p)));
    return v;
}

// ---------------------------------------------------------------------------
// prepN (32x32 tiles): N[hp][h*128+k][d'] = sum_d W0[k,h128+d]*W1[h128+d,hp128+d']
// grid (4,4,16), 256 threads.
// ---------------------------------------------------------------------------
__global__ __launch_bounds__(256)
void prepN_kernel(const float* __restrict__ W0, const float* __restrict__ W1,
                  float* __restrict__ Nmat)
{
    const int z = blockIdx.z;
    const int hp = z >> 2, h = z & 3;
    const float* A = W0 + h * 128;                                  // [128 x 128], lda 512
    const float* B = W1 + (size_t)(h * 128) * 512 + hp * 128;       // [128 x 128], ldb 512
    float* C = Nmat + (size_t)hp * 65536 + (size_t)(h * 128) * 128; // ldc 128

    const int M0 = blockIdx.y * 32;
    const int N0 = blockIdx.x * 32;
    const int tx = threadIdx.x & 15;
    const int ty = threadIdx.x >> 4;
    const int tid = threadIdx.x;

    __shared__ float As[16][32];
    __shared__ float Bs[16][32];

    float acc[2][2] = {{0.f, 0.f}, {0.f, 0.f}};

    for (int k0 = 0; k0 < 128; k0 += 16) {
        if (tid < 128) {
            int r = tid >> 2, c4 = (tid & 3) * 4;
            float4 av = *(const float4*)(A + (size_t)(M0 + r) * 512 + k0 + c4);
            As[c4 + 0][r] = av.x;
            As[c4 + 1][r] = av.y;
            As[c4 + 2][r] = av.z;
            As[c4 + 3][r] = av.w;
        } else {
            int t = tid - 128;
            int r = t >> 3, c4 = (t & 7) * 4;
            float4 bv = *(const float4*)(B + (size_t)(k0 + r) * 512 + N0 + c4);
            *(float4*)&Bs[r][c4] = bv;
        }
        __syncthreads();
        #pragma unroll
        for (int k = 0; k < 16; k++) {
            float a0 = As[k][ty * 2], a1 = As[k][ty * 2 + 1];
            float b0 = Bs[k][tx * 2], b1 = Bs[k][tx * 2 + 1];
            acc[0][0] = fmaf(a0, b0, acc[0][0]);
            acc[0][1] = fmaf(a0, b1, acc[0][1]);
            acc[1][0] = fmaf(a1, b0, acc[1][0]);
            acc[1][1] = fmaf(a1, b1, acc[1][1]);
        }
        __syncthreads();
    }
    #pragma unroll
    for (int i = 0; i < 2; i++)
        #pragma unroll
        for (int j = 0; j < 2; j++)
            C[(size_t)(M0 + ty * 2 + i) * 128 + N0 + tx * 2 + j] = acc[i][j];
}

// ---------------------------------------------------------------------------
// prepQP: blocks 0..15 compute Q from N (Q = N @ a1, exact); blocks 16..19
// compute P0 = W0_h @ a0. 128 threads.
// ---------------------------------------------------------------------------
__global__ __launch_bounds__(128)
void prepQP_kernel(const float* __restrict__ Nmat,
                   const float* __restrict__ a1s, const float* __restrict__ a1n,
                   const float* __restrict__ W0,
                   const float* __restrict__ a0s, const float* __restrict__ a0n,
                   float* __restrict__ Q, float* __restrict__ P0)
{
    const int b = blockIdx.x;
    const int tid = threadIdx.x;
    if (b < 16) {
        const int hp = b >> 2, h = b & 3;
        __shared__ float sa1s[128], sa1n[128];
        sa1s[tid] = a1s[hp * 128 + tid];
        sa1n[tid] = a1n[hp * 128 + tid];
        __syncthreads();
        const float* nrow = Nmat + (size_t)hp * 65536 + (size_t)(h * 128 + tid) * 128;
        float s = 0.f, n = 0.f;
        #pragma unroll 4
        for (int d = 0; d < 128; d++) {
            float nv = nrow[d];
            s = fmaf(nv, sa1s[d], s);
            n = fmaf(nv, sa1n[d], n);
        }
        Q[hp * 512 + h * 128 + tid] = s;
        Q[2048 + hp * 512 + h * 128 + tid] = n;
    } else {
        const int t = (b - 16) * 128 + tid;   // 0..511 = (h,f)
        const int h = t >> 7, f = t & 127;
        const float* wrow = W0 + (size_t)f * 512 + h * 128;
        const float* as = a0s + h * 128;
        const float* an = a0n + h * 128;
        float s = 0.f, n = 0.f;
        #pragma unroll 4
        for (int d = 0; d < 128; d++) {
            float wv = wrow[d];
            s = fmaf(wv, as[d], s);
            n = fmaf(wv, an[d], n);
        }
        P0[t] = s;
        P0[512 + t] = n;
    }
}

// ---------------------------------------------------------------------------
// fp32 GEMM: C = A@B, 64x64 tile, BK=16, 256 threads, 4x4/thread,
// register double-buffering of the next K-tile.
// ---------------------------------------------------------------------------
__global__ __launch_bounds__(256)
void gemm_kernel(const float* __restrict__ A, const float* __restrict__ B,
                 float* __restrict__ C,
                 int K, int lda, int ldb, int ldc,
                 int offA, int offB, int offC)
{
    A += (size_t)blockIdx.z * offA;
    B += (size_t)blockIdx.z * offB;
    C += (size_t)blockIdx.z * offC;

    const int row0 = blockIdx.y * 64;
    const int col0 = blockIdx.x * 64;
    const int tx = threadIdx.x;
    const int ty = threadIdx.y;
    const int tid = ty * 16 + tx;

    __shared__ float As[16][64];
    __shared__ float Bs[16][64];

    const int ar = tid >> 2;
    const int ac = (tid & 3) * 4;
    const int br = tid >> 4;
    const int bc = (tid & 15) * 4;

    float acc[4][4];
    #pragma unroll
    for (int i = 0; i < 4; i++)
        #pragma unroll
        for (int j = 0; j < 4; j++) acc[i][j] = 0.f;

    const int nt = K >> 4;
    float4 av = *(const float4*)(A + (size_t)(row0 + ar) * lda + ac);
    float4 bv = *(const float4*)(B + (size_t)br * ldb + col0 + bc);

    for (int i = 0; i < nt; i++) {
        As[ac + 0][ar] = av.x;
        As[ac + 1][ar] = av.y;
        As[ac + 2][ar] = av.z;
        As[ac + 3][ar] = av.w;
        *(float4*)&Bs[br][bc] = bv;
        __syncthreads();

        if (i + 1 < nt) {
            int k0 = (i + 1) << 4;
            av = *(const float4*)(A + (size_t)(row0 + ar) * lda + k0 + ac);
            bv = *(const float4*)(B + (size_t)(k0 + br) * ldb + col0 + bc);
        }

        #pragma unroll
        for (int k = 0; k < 16; k++) {
            float4 a4 = *(const float4*)&As[k][ty * 4];
            float4 b4 = *(const float4*)&Bs[k][tx * 4];
            float a[4] = {a4.x, a4.y, a4.z, a4.w};
            float b[4] = {b4.x, b4.y, b4.z, b4.w};
            #pragma unroll
            for (int ii = 0; ii < 4; ii++)
                #pragma unroll
                for (int jj = 0; jj < 4; jj++)
                    acc[ii][jj] = fmaf(a[ii], b[jj], acc[ii][jj]);
        }
        __syncthreads();
    }

    #pragma unroll
    for (int i = 0; i < 4; i++) {
        float4 o = {acc[i][0], acc[i][1], acc[i][2], acc[i][3]};
        *(float4*)(C + (size_t)(row0 + ty * 4 + i) * ldc + col0 + tx * 4) = o;
    }
}

// ---------------------------------------------------------------------------
// F=128 attention, both levels fused (unchanged from R5).
// ---------------------------------------------------------------------------
__global__ __launch_bounds__(128)
void attn128_kernel(const float* __restrict__ h0, const float* __restrict__ h1,
                    const float* __restrict__ h2,
                    const float* __restrict__ Ws, const float* __restrict__ Wn,
                    float* __restrict__ y1, float* __restrict__ y0, int G1)
{
    __shared__ float sxn[25 * 128];
    __shared__ float slog[26 * 4];
    __shared__ float salpha[25 * 4];
    __shared__ uint64_t mbar_s;

    const int b = blockIdx.x;
    const bool big = b < G1;
    const int g = big ? b : b - G1;
    const int E = big ? 25 : 10;
    const float* gxn = big ? (h2 + (size_t)g * 25 * 128) : (h1 + (size_t)g * 10 * 128);
    const float* gxs = big ? (h1 + (size_t)g * 128) : (h0 + (size_t)g * 128);
    float* gy = (big ? y1 : y0) + (size_t)g * 512;

    const int tid  = threadIdx.x;
    const int w    = tid >> 5;
    const int lane = tid & 31;
    const uint32_t mbar = smem_u32(&mbar_s);

    if (tid == 0) {
        mbar_init(mbar, 1);
        asm volatile("fence.proxy.async.shared::cta;" ::: "memory");
    }
    __syncthreads();
    if (tid == 0) {
        mbar_expect_tx(mbar, (uint32_t)(E * 128 * 4));
        bulk_g2s(smem_u32(sxn), gxn, (uint32_t)(E * 128 * 4), mbar);
    }

    const int hh = lane & 3;
    const int s  = lane >> 2;
    float4 wq[4];
    #pragma unroll
    for (int j = 0; j < 4; j++) wq[j] = ldg4(Wn + hh * 128 + 4 * (s + 8 * j));

    if (w == 0) {
        float acc = 0.f;
        #pragma unroll
        for (int j = 0; j < 4; j++)
            acc = dot4(ldg4(gxs + 4 * (s + 8 * j)),
                       ldg4(Ws + hh * 128 + 4 * (s + 8 * j)), acc);
        acc += __shfl_xor_sync(0xffffffffu, acc, 4);
        acc += __shfl_xor_sync(0xffffffffu, acc, 8);
        acc += __shfl_xor_sync(0xffffffffu, acc, 16);
        if (lane < 4) slog[E * 4 + lane] = acc;
    }

    mbar_wait(mbar, 0);

    for (int e = w; e < E; e += 4) {
        const float* xp = &sxn[e * 128];
        float acc = 0.f;
        #pragma unroll
        for (int j = 0; j < 4; j++)
            acc = dot4(lds4(xp + 4 * (s + 8 * j)), wq[j], acc);
        acc += __shfl_xor_sync(0xffffffffu, acc, 4);
        acc += __shfl_xor_sync(0xffffffffu, acc, 8);
        acc += __shfl_xor_sync(0xffffffffu, acc, 16);
        if (lane < 4) slog[e * 4 + lane] = acc;
    }
    __syncthreads();

    {
        float es = slog[E * 4 + w];
        float v;
        if (lane < E) {
            float l = es + slog[lane * 4 + w];
            v = (l >= 0.f) ? l : 0.2f * l;
        } else {
            v = -3.4e38f;
        }
        float m = v;
        #pragma unroll
        for (int o = 16; o; o >>= 1) m = fmaxf(m, __shfl_xor_sync(0xffffffffu, m, o));
        float p = (lane < E) ? __expf(v - m) : 0.f;
        float sum = p;
        #pragma unroll
        for (int o = 16; o; o >>= 1) sum += __shfl_xor_sync(0xffffffffu, sum, o);
        if (lane < E) salpha[lane * 4 + w] = p / sum;
    }
    __syncthreads();

    float acc[4] = {0.f, 0.f, 0.f, 0.f};
    for (int e = 0; e < E; e++) {
        float val = sxn[e * 128 + tid];
        #pragma unroll
        for (int q = 0; q < 4; q++) acc[q] = fmaf(salpha[e * 4 + q], val, acc[q]);
    }
    #pragma unroll
    for (int q = 0; q < 4; q++) gy[q * 128 + tid] = acc[q];
}

// ---------------------------------------------------------------------------
// F=512, E=10 attention (unchanged from R5).
// ---------------------------------------------------------------------------
__global__ __launch_bounds__(128)
void attn512_kernel(const float* __restrict__ xs, const float* __restrict__ xn,
                    const float* __restrict__ Ws, const float* __restrict__ Wn,
                    float* __restrict__ y)
{
    constexpr int E = 10, F = 512;
    __shared__ float sxn[E * F];
    __shared__ float slog[(E + 1) * 4];
    __shared__ float salpha[E * 4];
    __shared__ uint64_t mbar_s;

    const int g    = blockIdx.x;
    const int tid  = threadIdx.x;
    const int w    = tid >> 5;
    const int lane = tid & 31;
    const uint32_t mbar = smem_u32(&mbar_s);
    const float* gxn = xn + (size_t)g * E * F;
    const float* gxs = xs + (size_t)g * F;

    if (tid == 0) {
        mbar_init(mbar, 1);
        asm volatile("fence.proxy.async.shared::cta;" ::: "memory");
    }
    __syncthreads();
    if (tid == 0) {
        mbar_expect_tx(mbar, E * F * 4);
        bulk_g2s(smem_u32(sxn), gxn, E * F * 4, mbar);
    }

    float4 wq[4];
    #pragma unroll
    for (int j = 0; j < 4; j++) wq[j] = ldg4(Wn + w * F + 4 * (lane + 32 * j));

    {
        float acc = 0.f;
        #pragma unroll
        for (int j = 0; j < 4; j++)
            acc = dot4(ldg4(gxs + 4 * (lane + 32 * j)),
                       ldg4(Ws + w * F + 4 * (lane + 32 * j)), acc);
        #pragma unroll
        for (int o = 16; o; o >>= 1) acc += __shfl_xor_sync(0xffffffffu, acc, o);
        if (lane == 0) slog[E * 4 + w] = acc;
    }

    mbar_wait(mbar, 0);

    for (int e = 0; e < E; e++) {
        const float* xp = &sxn[e * F];
        float acc = 0.f;
        #pragma unroll
        for (int j = 0; j < 4; j++)
            acc = dot4(lds4(xp + 4 * (lane + 32 * j)), wq[j], acc);
        #pragma unroll
        for (int o = 16; o; o >>= 1) acc += __shfl_xor_sync(0xffffffffu, acc, o);
        if (lane == 0) slog[e * 4 + w] = acc;
    }
    __syncthreads();

    {
        float es = slog[E * 4 + w];
        float v;
        if (lane < E) {
            float l = es + slog[lane * 4 + w];
            v = (l >= 0.f) ? l : 0.2f * l;
        } else {
            v = -3.4e38f;
        }
        float m = v;
        #pragma unroll
        for (int o = 16; o; o >>= 1) m = fmaxf(m, __shfl_xor_sync(0xffffffffu, m, o));
        float p = (lane < E) ? __expf(v - m) : 0.f;
        float sum = p;
        #pragma unroll
        for (int o = 16; o; o >>= 1) sum += __shfl_xor_sync(0xffffffffu, sum, o);
        if (lane < E) salpha[lane * 4 + w] = p / sum;
    }
    __syncthreads();

    float acc[4][4];
    #pragma unroll
    for (int c = 0; c < 4; c++)
        #pragma unroll
        for (int q = 0; q < 4; q++) acc[c][q] = 0.f;
    for (int e = 0; e < E; e++) {
        float al[4];
        #pragma unroll
        for (int q = 0; q < 4; q++) al[q] = salpha[e * 4 + q];
        #pragma unroll
        for (int c = 0; c < 4; c++) {
            float val = sxn[e * F + c * 128 + tid];
            #pragma unroll
            for (int q = 0; q < 4; q++) acc[c][q] = fmaf(al[q], val, acc[c][q]);
        }
    }
    float* gy = y + (size_t)g * (4 * F);
    #pragma unroll
    for (int q = 0; q < 4; q++)
        #pragma unroll
        for (int c = 0; c < 4; c++)
            gy[q * F + c * 128 + tid] = acc[c][q];
}

// ---------------------------------------------------------------------------
extern "C" void kernel_launch(void* const* d_in, const int* in_sizes, int n_in,
                              void* d_out, int out_size)
{
    const float* h0  = (const float*)d_in[0];
    const float* h1  = (const float*)d_in[1];
    const float* h2  = (const float*)d_in[2];
    const float* W0  = (const float*)d_in[3];
    const float* a0s = (const float*)d_in[4];
    const float* a0n = (const float*)d_in[5];
    const float* W1  = (const float*)d_in[6];
    const float* a1s = (const float*)d_in[7];
    const float* a1n = (const float*)d_in[8];
    const float* Wfc = (const float*)d_in[9];
    float* out = (float*)d_out;

    float* scr = nullptr;
    cudaGetSymbolAddress((void**)&scr, g_scratch);
    float* y1   = scr + OFF_Y1;
    float* y0   = scr + OFF_Y0;
    float* u    = scr + OFF_U;
    float* hs0  = scr + OFF_H;
    float* P0   = scr + OFF_P0;
    float* Q    = scr + OFF_Q;
    float* Nmat = scr + OFF_N;

    // N = blockdiag(W0) @ W1  (16 x 128^3 tiles, 256 blocks)
    prepN_kernel<<<dim3(4, 4, 16), 256>>>(W0, W1, Nmat);
    // Q = N @ a1 (exact), and P0 = W0_h @ a0
    prepQP_kernel<<<20, 128>>>(Nmat, a1s, a1n, W0, a0s, a0n, Q, P0);

    // both F=128 attentions in one launch
    attn128_kernel<<<10240 + 1024, 128>>>(h0, h1, h2, P0, P0 + 512, y1, y0, 10240);

    // layer-1 attention -> u [1024, 4(h'), 512]
    attn512_kernel<<<1024, 128>>>(y0, y1, Q, Q + 2048, u);

    // hs0[g, hp*128+d'] = u[g,hp,:] @ N[hp]   (per-hp batched)
    gemm_kernel<<<dim3(2, 16, 4), dim3(16, 16)>>>(u, Nmat, hs0, 512, 2048, 128, 512,
                                                  512, 512 * 128, 128);
    // out = hs0 @ Wfc
    gemm_kernel<<<dim3(4, 16, 1), dim3(16, 16)>>>(hs0, Wfc, out, 512, 512, 256, 256,
                                                  0, 0, 0);
}